// round 16
// baseline (speedup 1.0000x reference)
#include <cuda_runtime.h>
#include <cuda_bf16.h>
#include <cstdint>

#define BB 8
#define LL 2048
#define PP 32
#define DD 256
#define NXX 16
#define NT (BB*LL)   // 16384 tokens
#define NBLK 256
#define SMEM_BYTES 99328   // 24832 floats

typedef unsigned long long ull;

// ---------------- scratch (device globals; no allocation allowed) ----------------
__device__ float g_h  [NT*DD];
__device__ float g_hn [NT*DD];
__device__ float g_dl2[NT];        // delta * log2(e)
__device__ float g_dB [NT*NXX];    // delta * Bm
__device__ float g_C  [NT*NXX];
__device__ float g_upd[NT*DD];

// grid barrier state (2 instances); gen is monotonic across graph replays
__device__ unsigned g_barcnt[2];
__device__ volatile unsigned g_bargen[2];

// ---------------- helpers ----------------
__device__ __forceinline__ float fexp2(float x){
    float r; asm("ex2.approx.f32 %0, %1;" : "=f"(r) : "f"(x)); return r;
}
__device__ __forceinline__ float softplusf(float x){
    return x > 20.f ? x : log1pf(expf(x));
}
__device__ __forceinline__ float geluf(float x){
    return 0.5f * x * (1.f + erff(x * 0.70710678118654752f));
}
__device__ __forceinline__ ull packdup(float v){
    ull r; asm("mov.b64 %0, {%1, %1};" : "=l"(r) : "f"(v)); return r;
}
#define FFMA2(acc, a, b) asm("fma.rn.f32x2 %0, %1, %2, %0;" : "+l"(acc) : "l"(a), "l"(b))
__device__ __forceinline__ float2 unpack2(ull p){
    float lo, hi; asm("mov.b64 {%0, %1}, %2;" : "=f"(lo), "=f"(hi) : "l"(p));
    float2 r; r.x = lo; r.y = hi; return r;
}

// software grid barrier: safe because all NBLK blocks are guaranteed co-resident
__device__ __forceinline__ void gridbar(int i){
    __syncthreads();
    if (threadIdx.x == 0){
        unsigned gen = g_bargen[i];          // read BEFORE arrive
        __threadfence();                     // publish this block's writes + order gen read
        if (atomicAdd(&g_barcnt[i], 1u) == (unsigned)(NBLK - 1)){
            g_barcnt[i] = 0u;
            __threadfence();
            g_bargen[i] = gen + 1u;          // release
        } else {
            while (g_bargen[i] == gen) __nanosleep(64);
            __threadfence();                 // acquire
        }
    }
    __syncthreads();
}

// =====================================================================
// MEGA kernel: stage1 (in-proj + LN + delta/B/C)  | gridbar |
//              stage2 (selective scan)            | gridbar |
//              stage3 (LN + MLP gelu + out-proj)
// 256 blocks x 256 threads, 2 CTAs/SM, dyn smem 99328 B
// =====================================================================
#define SVS 260
__global__ void __launch_bounds__(256, 2) mega(const float* __restrict__ y,
                                               const float* __restrict__ Win,
                                               const float* __restrict__ bin,
                                               const float* __restrict__ ng,
                                               const float* __restrict__ nb,
                                               const float* __restrict__ A,
                                               const float* __restrict__ W_B,
                                               const float* __restrict__ W_C,
                                               const float* __restrict__ qd,
                                               const float* __restrict__ pd,
                                               const float* __restrict__ nfg,
                                               const float* __restrict__ nfb,
                                               const float* __restrict__ W1,
                                               const float* __restrict__ b1,
                                               const float* __restrict__ W2,
                                               const float* __restrict__ b2,
                                               float* __restrict__ out){
    extern __shared__ float smf[];
    int tid  = threadIdx.x;
    int bid  = blockIdx.x;
    int lane = tid & 31, wrp = tid >> 5;

    // ================= STAGE 1: 64 tokens per block ====================
    {
        float* sy  = smf;               // [16][32]
        float* sh  = smf + 512;         // [16][256]
        float* shn = smf + 4608;        // [16][256]
        float* sw  = smf + 8704;        // [33][256] row0=q_delta,1..16=W_B,17..32=W_C

        // projection weights: loaded once, used for 4 sub-tiles
        #pragma unroll
        for (int it = 0; it < 33; it++){
            int idx = tid + it*256;
            int row = idx >> 8, c = idx & 255;
            float v = (row == 0) ? qd[c] : (row <= 16 ? W_B[(row-1)*DD + c]
                                                      : W_C[(row-17)*DD + c]);
            sw[row*DD + c] = v;
        }
        float pd0 = pd[0];

        int d = tid;
        float wcol[PP];
        #pragma unroll
        for (int p = 0; p < PP; p++) wcol[p] = Win[p*DD + d];
        float bi = bin[d];
        float4 gA = *(const float4*)&ng[lane*8], gB = *(const float4*)&ng[lane*8+4];
        float4 bA = *(const float4*)&nb[lane*8], bB = *(const float4*)&nb[lane*8+4];

        for (int s = 0; s < 4; s++){
            int tok0 = bid*64 + s*16;
            __syncthreads();   // protect sy/sh/shn reuse across sub-tiles
            sy[tid]       = y[(size_t)tok0*PP + tid];
            sy[tid + 256] = y[(size_t)tok0*PP + tid + 256];
            __syncthreads();

            // phase A: h = y @ Win + bin (thread = one d), dual accumulator
            #pragma unroll 4
            for (int t = 0; t < 16; t++){
                const float4* yt = (const float4*)&sy[t*PP];
                float hA = bi, hB = 0.f;
                #pragma unroll
                for (int p4 = 0; p4 < 4; p4++){
                    float4 yv = yt[p4];
                    hA = fmaf(wcol[p4*4+0], yv.x, hA);
                    hA = fmaf(wcol[p4*4+1], yv.y, hA);
                    hA = fmaf(wcol[p4*4+2], yv.z, hA);
                    hA = fmaf(wcol[p4*4+3], yv.w, hA);
                }
                #pragma unroll
                for (int p4 = 4; p4 < 8; p4++){
                    float4 yv = yt[p4];
                    hB = fmaf(wcol[p4*4+0], yv.x, hB);
                    hB = fmaf(wcol[p4*4+1], yv.y, hB);
                    hB = fmaf(wcol[p4*4+2], yv.z, hB);
                    hB = fmaf(wcol[p4*4+3], yv.w, hB);
                }
                float h = hA + hB;
                sh[t*DD + d] = h;
                g_h[(size_t)(tok0 + t)*DD + d] = h;
            }
            __syncthreads();

            // phase LN: warp per 2 tokens, lane holds 8 d's
            #pragma unroll
            for (int t = 0; t < 2; t++){
                int tok = wrp*2 + t;
                float4 h0 = *(const float4*)&sh[tok*DD + lane*8];
                float4 h1 = *(const float4*)&sh[tok*DD + lane*8 + 4];
                float su_ = (h0.x+h0.y)+(h0.z+h0.w)+(h1.x+h1.y)+(h1.z+h1.w);
                float s2 = h0.x*h0.x+h0.y*h0.y+h0.z*h0.z+h0.w*h0.w
                         + h1.x*h1.x+h1.y*h1.y+h1.z*h1.z+h1.w*h1.w;
                #pragma unroll
                for (int o = 16; o; o >>= 1){
                    su_ += __shfl_xor_sync(0xffffffffu, su_, o);
                    s2  += __shfl_xor_sync(0xffffffffu, s2,  o);
                }
                float mu   = su_ * (1.f/DD);
                float var  = s2 * (1.f/DD) - mu*mu;
                float rstd = rsqrtf(var + 1e-5f);
                float4 n0, n1;
                n0.x=(h0.x-mu)*rstd*gA.x+bA.x; n0.y=(h0.y-mu)*rstd*gA.y+bA.y;
                n0.z=(h0.z-mu)*rstd*gA.z+bA.z; n0.w=(h0.w-mu)*rstd*gA.w+bA.w;
                n1.x=(h1.x-mu)*rstd*gB.x+bB.x; n1.y=(h1.y-mu)*rstd*gB.y+bB.y;
                n1.z=(h1.z-mu)*rstd*gB.z+bB.z; n1.w=(h1.w-mu)*rstd*gB.w+bB.w;
                *(float4*)&shn[tok*DD + lane*8]     = n0;
                *(float4*)&shn[tok*DD + lane*8 + 4] = n1;
                *(float4*)&g_hn[(size_t)(tok0+tok)*DD + lane*8]     = n0;
                *(float4*)&g_hn[(size_t)(tok0+tok)*DD + lane*8 + 4] = n1;
            }
            __syncthreads();

            // phase B: thread = (tok, sub); sub covers d = sub*4 + 64j
            {
                int tok = tid >> 4, sub = tid & 15;
                const float* hrow = &shn[tok*DD];
                ull ha[8];
                #pragma unroll
                for (int j = 0; j < 4; j++){
                    float4 hv = *(const float4*)&hrow[sub*4 + 64*j];
                    asm("mov.b64 %0, {%1, %2};" : "=l"(ha[2*j])   : "f"(hv.x), "f"(hv.y));
                    asm("mov.b64 %0, {%1, %2};" : "=l"(ha[2*j+1]) : "f"(hv.z), "f"(hv.w));
                }
                int tg = tok0 + tok;
                float delta = 0.f, myB = 0.f, myC = 0.f;

                #pragma unroll
                for (int c = 0; c <= 16; c++){
                    ull a0 = 0ull, a1 = 0ull;
                    const float* wr = &sw[c*DD];
                    #pragma unroll
                    for (int j = 0; j < 4; j++){
                        ulonglong2 wv = *(const ulonglong2*)&wr[sub*4 + 64*j];
                        FFMA2(a0, ha[2*j],   wv.x);
                        FFMA2(a1, ha[2*j+1], wv.y);
                    }
                    float2 u = unpack2(a0), v = unpack2(a1);
                    float ss = (u.x + u.y) + (v.x + v.y);
                    ss += __shfl_xor_sync(0xffffffffu, ss, 1);
                    ss += __shfl_xor_sync(0xffffffffu, ss, 2);
                    ss += __shfl_xor_sync(0xffffffffu, ss, 4);
                    ss += __shfl_xor_sync(0xffffffffu, ss, 8);
                    if (c == 0)            delta = ss;
                    else if (sub == c - 1) myB   = ss;
                }
                delta = softplusf(pd0 + delta);
                g_dB[tg*NXX + sub] = delta * myB;
                if (sub == 0) g_dl2[tg] = delta * 1.44269504088896f;

                #pragma unroll
                for (int c = 17; c < 33; c++){
                    ull a0 = 0ull, a1 = 0ull;
                    const float* wr = &sw[c*DD];
                    #pragma unroll
                    for (int j = 0; j < 4; j++){
                        ulonglong2 wv = *(const ulonglong2*)&wr[sub*4 + 64*j];
                        FFMA2(a0, ha[2*j],   wv.x);
                        FFMA2(a1, ha[2*j+1], wv.y);
                    }
                    float2 u = unpack2(a0), v = unpack2(a1);
                    float ss = (u.x + u.y) + (v.x + v.y);
                    ss += __shfl_xor_sync(0xffffffffu, ss, 1);
                    ss += __shfl_xor_sync(0xffffffffu, ss, 2);
                    ss += __shfl_xor_sync(0xffffffffu, ss, 4);
                    ss += __shfl_xor_sync(0xffffffffu, ss, 8);
                    if (sub == c - 17) myC = ss;
                }
                g_C[tg*NXX + sub] = myC;
            }
        }
    }

    gridbar(0);

    // ================= STAGE 2: selective scan (blocks 0..127) =========
    if (bid < 128){
        float* sdl2 = smf;           // [32]
        float* sdb  = smf + 32;      // [32*16]
        float* sc   = smf + 544;     // [32*16]
        float* su   = smf + 1056;    // [32*16]
        float* scx  = smf + 1568;    // [32*256]

        int n = tid & 15, dl = tid >> 4;
        int b = bid >> 4, d0 = (bid & 15) * 16;
        float a = A[(d0 + dl)*NXX + n];
        float x = 0.f;
        size_t tbase = (size_t)b * LL;

        // prefetch tile 0 into registers
        float pdb[2], pc[2], pu[2], pdl = 0.f;
        if (tid < 32) pdl = g_dl2[tbase + tid];
        #pragma unroll
        for (int r = 0; r < 2; r++){
            int idx = tid + r*256;
            int tt = idx >> 4, q = idx & 15;
            pdb[r] = g_dB[(tbase + tt)*NXX + q];
            pc [r] = g_C [(tbase + tt)*NXX + q];
            pu [r] = g_hn[(tbase + tt)*DD + d0 + q];
        }

        for (int t0 = 0; t0 < LL; t0 += 32){
            if (tid < 32) sdl2[tid] = pdl;
            #pragma unroll
            for (int r = 0; r < 2; r++){
                int idx = tid + r*256;
                sdb[idx] = pdb[r]; sc[idx] = pc[r]; su[idx] = pu[r];
            }
            __syncthreads();
            if (t0 + 32 < LL){
                int t1 = t0 + 32;
                if (tid < 32) pdl = g_dl2[tbase + t1 + tid];
                #pragma unroll
                for (int r = 0; r < 2; r++){
                    int idx = tid + r*256;
                    int tt = idx >> 4, q = idx & 15;
                    pdb[r] = g_dB[(tbase + t1 + tt)*NXX + q];
                    pc [r] = g_C [(tbase + t1 + tt)*NXX + q];
                    pu [r] = g_hn[(tbase + t1 + tt)*DD + d0 + q];
                }
            }
            #pragma unroll 4
            for (int tt = 0; tt < 32; tt++){
                float dA  = fexp2(sdl2[tt] * a);
                float dbu = sdb[tt*16 + n] * su[tt*16 + dl];
                x = fmaf(dA, x, dbu);
                scx[tt*256 + dl*16 + n] = x * sc[tt*16 + n];
            }
            __syncthreads();
            #pragma unroll
            for (int r = 0; r < 2; r++){
                int c = tid + r*256;
                int tt = c >> 4, dd = c & 15;
                const float4* p = (const float4*)&scx[tt*256 + dd*16];
                float4 v0 = p[0], v1 = p[1], v2 = p[2], v3 = p[3];
                float s = ((v0.x+v0.y)+(v0.z+v0.w)) + ((v1.x+v1.y)+(v1.z+v1.w))
                        + ((v2.x+v2.y)+(v2.z+v2.w)) + ((v3.x+v3.y)+(v3.z+v3.w));
                g_upd[(tbase + t0 + tt)*DD + d0 + dd] = s;
            }
            __syncthreads();
        }
    }

    gridbar(1);

    // ================= STAGE 3: LN + MLP + out-proj (64 tokens) ========
    {
        float* sv = smf;                 // [64][SVS]
        float* Bs = smf + 64*SVS;        // [32][256] W1 chunk, later [256][32] W2
        int tok0 = bid * 64;

        // phase 1: LN(h + upd) -> sv
        {
            float4 gA = *(const float4*)&nfg[lane*8], gB = *(const float4*)&nfg[lane*8+4];
            float4 bA = *(const float4*)&nfb[lane*8], bB = *(const float4*)&nfb[lane*8+4];
            #pragma unroll
            for (int t = 0; t < 8; t++){
                int tok = wrp*8 + t;
                size_t base = (size_t)(tok0 + tok)*DD + lane*8;
                float4 h0 = *(const float4*)&g_h[base];
                float4 h1 = *(const float4*)&g_h[base+4];
                float4 u0 = *(const float4*)&g_upd[base];
                float4 u1 = *(const float4*)&g_upd[base+4];
                float4 v0, v1;
                v0.x=h0.x+u0.x; v0.y=h0.y+u0.y; v0.z=h0.z+u0.z; v0.w=h0.w+u0.w;
                v1.x=h1.x+u1.x; v1.y=h1.y+u1.y; v1.z=h1.z+u1.z; v1.w=h1.w+u1.w;
                float s  = (v0.x+v0.y)+(v0.z+v0.w)+(v1.x+v1.y)+(v1.z+v1.w);
                float s2 = v0.x*v0.x+v0.y*v0.y+v0.z*v0.z+v0.w*v0.w
                         + v1.x*v1.x+v1.y*v1.y+v1.z*v1.z+v1.w*v1.w;
                #pragma unroll
                for (int o = 16; o; o >>= 1){
                    s  += __shfl_xor_sync(0xffffffffu, s,  o);
                    s2 += __shfl_xor_sync(0xffffffffu, s2, o);
                }
                float mu   = s * (1.f/DD);
                float var  = s2 * (1.f/DD) - mu*mu;
                float rstd = rsqrtf(var + 1e-5f);
                float4 n0, n1;
                n0.x=(v0.x-mu)*rstd*gA.x+bA.x; n0.y=(v0.y-mu)*rstd*gA.y+bA.y;
                n0.z=(v0.z-mu)*rstd*gA.z+bA.z; n0.w=(v0.w-mu)*rstd*gA.w+bA.w;
                n1.x=(v1.x-mu)*rstd*gB.x+bB.x; n1.y=(v1.y-mu)*rstd*gB.y+bB.y;
                n1.z=(v1.z-mu)*rstd*gB.z+bB.z; n1.w=(v1.w-mu)*rstd*gB.w+bB.w;
                *(float4*)&sv[tok*SVS + lane*8]     = n0;
                *(float4*)&sv[tok*SVS + lane*8 + 4] = n1;
            }
        }
        __syncthreads();

        // phase 2: G = gelu(sv @ W1 + b1)
        int tx = tid & 31, ty = tid >> 5;
        ull acc[8][4];
        #pragma unroll
        for (int i = 0; i < 8; i++)
            #pragma unroll
            for (int j = 0; j < 4; j++) acc[i][j] = 0ull;

        for (int kk = 0; kk < DD; kk += 32){
            #pragma unroll
            for (int r = 0; r < 8; r++){
                int f4 = tid + r*256;
                int row = f4 >> 6, c4 = (f4 & 63) << 2;
                *(float4*)&Bs[row*256 + c4] =
                    *(const float4*)&W1[(size_t)(kk + row)*DD + c4];
            }
            __syncthreads();
            #pragma unroll 8
            for (int k = 0; k < 32; k++){
                ulonglong2 p0 = *(const ulonglong2*)&Bs[k*256 + tx*4];
                ulonglong2 p1 = *(const ulonglong2*)&Bs[k*256 + 128 + tx*4];
                #pragma unroll
                for (int i = 0; i < 8; i++){
                    ull a2 = packdup(sv[(ty*8+i)*SVS + kk + k]);
                    FFMA2(acc[i][0], a2, p0.x);
                    FFMA2(acc[i][1], a2, p0.y);
                    FFMA2(acc[i][2], a2, p1.x);
                    FFMA2(acc[i][3], a2, p1.y);
                }
            }
            __syncthreads();
        }

        // gelu + bias -> back into sv
        {
            float4 bb0 = *(const float4*)&b1[tx*4];
            float4 bb1 = *(const float4*)&b1[128 + tx*4];
            float bias[8] = {bb0.x,bb0.y,bb0.z,bb0.w,bb1.x,bb1.y,bb1.z,bb1.w};
            #pragma unroll
            for (int i = 0; i < 8; i++){
                int tok = ty*8 + i;
                #pragma unroll
                for (int j = 0; j < 4; j++){
                    float2 u = unpack2(acc[i][j]);
                    float2 o;
                    o.x = geluf(u.x + bias[2*j]);
                    o.y = geluf(u.y + bias[2*j+1]);
                    int colbase = (j < 2) ? (tx*4 + 2*j) : (128 + tx*4 + 2*(j-2));
                    *(float2*)&sv[tok*SVS + colbase] = o;
                }
            }
        }
        // load W2 into Bs region ([256][32])
        #pragma unroll
        for (int r = 0; r < 8; r++){
            int f4 = (tid + r*256) << 2;
            *(float4*)&Bs[f4] = *(const float4*)&W2[f4];
        }
        __syncthreads();

        // phase 3: out = G @ W2 + b2
        {
            int tok = tid >> 2, og = tid & 3;
            float4 c0 = *(const float4*)&b2[og*8];
            float4 c1 = *(const float4*)&b2[og*8 + 4];
            ull o0, o1, o2, o3;
            asm("mov.b64 %0, {%1, %2};" : "=l"(o0) : "f"(c0.x), "f"(c0.y));
            asm("mov.b64 %0, {%1, %2};" : "=l"(o1) : "f"(c0.z), "f"(c0.w));
            asm("mov.b64 %0, {%1, %2};" : "=l"(o2) : "f"(c1.x), "f"(c1.y));
            asm("mov.b64 %0, {%1, %2};" : "=l"(o3) : "f"(c1.z), "f"(c1.w));
            #pragma unroll 4
            for (int k4 = 0; k4 < DD; k4 += 4){
                float4 g4 = *(const float4*)&sv[tok*SVS + k4];
                float ge[4] = {g4.x, g4.y, g4.z, g4.w};
                #pragma unroll
                for (int e = 0; e < 4; e++){
                    ull a2 = packdup(ge[e]);
                    const ull* wr = (const ull*)&Bs[(k4 + e)*32 + og*8];
                    FFMA2(o0, a2, wr[0]);
                    FFMA2(o1, a2, wr[1]);
                    FFMA2(o2, a2, wr[2]);
                    FFMA2(o3, a2, wr[3]);
                }
            }
            float2 r0 = unpack2(o0), r1 = unpack2(o1), r2 = unpack2(o2), r3 = unpack2(o3);
            float4 w0; w0.x=r0.x; w0.y=r0.y; w0.z=r1.x; w0.w=r1.y;
            float4 w1; w1.x=r2.x; w1.y=r2.y; w1.z=r3.x; w1.w=r3.y;
            size_t ob = (size_t)(tok0 + tok)*32 + og*8;
            *(float4*)&out[ob]     = w0;
            *(float4*)&out[ob + 4] = w1;
        }
    }
}

// ---------------- launcher ----------------
extern "C" void kernel_launch(void* const* d_in, const int* in_sizes, int n_in,
                              void* d_out, int out_size){
    (void)in_sizes; (void)n_in; (void)out_size;
    const float* y    = (const float*)d_in[0];
    const float* Win  = (const float*)d_in[1];
    const float* bin_ = (const float*)d_in[2];
    const float* ng   = (const float*)d_in[3];
    const float* nb   = (const float*)d_in[4];
    const float* A    = (const float*)d_in[5];
    const float* W_B  = (const float*)d_in[6];
    const float* W_C  = (const float*)d_in[7];
    const float* qd   = (const float*)d_in[8];
    const float* pd   = (const float*)d_in[9];
    const float* nfg  = (const float*)d_in[10];
    const float* nfb  = (const float*)d_in[11];
    const float* W1   = (const float*)d_in[12];
    const float* b1   = (const float*)d_in[13];
    const float* W2   = (const float*)d_in[14];
    const float* b2   = (const float*)d_in[15];
    float* out = (float*)d_out;

    cudaFuncSetAttribute(mega, cudaFuncAttributeMaxDynamicSharedMemorySize, SMEM_BYTES);

    mega<<<NBLK, 256, SMEM_BYTES>>>(y, Win, bin_, ng, nb, A, W_B, W_C, qd, pd,
                                    nfg, nfb, W1, b1, W2, b2, out);
}

// round 17
// speedup vs baseline: 1.0080x; 1.0080x over previous
#include <cuda_runtime.h>
#include <cuda_bf16.h>
#include <cstdint>

#define BB 8
#define LL 2048
#define PP 32
#define DD 256
#define NXX 16
#define NT (BB*LL)   // 16384 tokens

typedef unsigned long long ull;

// ---------------- scratch (device globals; no allocation allowed) ----------------
__device__ float g_h  [NT*DD];
__device__ float g_hn [NT*DD];
__device__ float g_dl2[NT];        // delta * log2(e)
__device__ float g_dB [NT*NXX];    // delta * Bm
__device__ float g_C  [NT*NXX];
__device__ float g_upd[NT*DD];

// ---------------- helpers ----------------
__device__ __forceinline__ float fexp2(float x){
    float r; asm("ex2.approx.f32 %0, %1;" : "=f"(r) : "f"(x)); return r;
}
__device__ __forceinline__ float softplusf(float x){
    return x > 20.f ? x : log1pf(expf(x));
}
__device__ __forceinline__ float geluf(float x){
    return 0.5f * x * (1.f + erff(x * 0.70710678118654752f));
}
__device__ __forceinline__ ull packdup(float v){
    ull r; asm("mov.b64 %0, {%1, %1};" : "=l"(r) : "f"(v)); return r;
}
#define FFMA2(acc, a, b) asm("fma.rn.f32x2 %0, %1, %2, %0;" : "+l"(acc) : "l"(a), "l"(b))
__device__ __forceinline__ float2 unpack2(ull p){
    float lo, hi; asm("mov.b64 {%0, %1}, %2;" : "=f"(lo), "=f"(hi) : "l"(p));
    float2 r; r.x = lo; r.y = hi; return r;
}

// =====================================================================
// K1: fused  h = y@Win + bin ;  hn = LN(h) ;  [delta | B | C] = proj(hn)
// 1024 blocks x 256 threads, 16 tokens/block  (unchanged from best)
// dyn smem (floats): sy[512] | sh[4096] | shn[4096] | sw[33*256] = 68608 B
// =====================================================================
__global__ void __launch_bounds__(256, 3) k1ab(const float* __restrict__ y,
                                               const float* __restrict__ Win,
                                               const float* __restrict__ bin,
                                               const float* __restrict__ ng,
                                               const float* __restrict__ nb,
                                               const float* __restrict__ W_B,
                                               const float* __restrict__ W_C,
                                               const float* __restrict__ qd,
                                               const float* __restrict__ pd){
    extern __shared__ float sm1[];
    float* sy  = sm1;               // [16][32]
    float* sh  = sm1 + 512;         // [16][256]
    float* shn = sm1 + 4608;        // [16][256]
    float* sw  = sm1 + 8704;        // [33][256]  row0=q_delta, 1..16=W_B, 17..32=W_C

    int tid  = threadIdx.x;
    int tok0 = blockIdx.x * 16;

    sy[tid]       = y[(size_t)tok0*PP + tid];
    sy[tid + 256] = y[(size_t)tok0*PP + tid + 256];
    #pragma unroll
    for (int it = 0; it < 33; it++){
        int idx = tid + it*256;
        int row = idx >> 8, c = idx & 255;
        float v = (row == 0) ? qd[c] : (row <= 16 ? W_B[(row-1)*DD + c]
                                                  : W_C[(row-17)*DD + c]);
        sw[row*DD + c] = v;
    }
    float pd0 = pd[0];

    // ---- phase A ----
    int d = tid;
    float wcol[PP];
    #pragma unroll
    for (int p = 0; p < PP; p++) wcol[p] = Win[p*DD + d];
    float bi = bin[d];
    __syncthreads();
    #pragma unroll 4
    for (int t = 0; t < 16; t++){
        const float4* yt = (const float4*)&sy[t*PP];
        float h = bi;
        #pragma unroll
        for (int p4 = 0; p4 < 8; p4++){
            float4 yv = yt[p4];
            h = fmaf(wcol[p4*4+0], yv.x, h);
            h = fmaf(wcol[p4*4+1], yv.y, h);
            h = fmaf(wcol[p4*4+2], yv.z, h);
            h = fmaf(wcol[p4*4+3], yv.w, h);
        }
        sh[t*DD + d] = h;
        g_h[(size_t)(tok0 + t)*DD + d] = h;
    }
    __syncthreads();

    // ---- phase LN ----
    int lane = tid & 31, wid = tid >> 5;
    {
        float4 gA = *(const float4*)&ng[lane*8], gB = *(const float4*)&ng[lane*8+4];
        float4 bA = *(const float4*)&nb[lane*8], bB = *(const float4*)&nb[lane*8+4];
        #pragma unroll
        for (int t = 0; t < 2; t++){
            int tok = wid*2 + t;
            float4 h0 = *(const float4*)&sh[tok*DD + lane*8];
            float4 h1 = *(const float4*)&sh[tok*DD + lane*8 + 4];
            float s  = (h0.x+h0.y)+(h0.z+h0.w)+(h1.x+h1.y)+(h1.z+h1.w);
            float s2 = h0.x*h0.x+h0.y*h0.y+h0.z*h0.z+h0.w*h0.w
                     + h1.x*h1.x+h1.y*h1.y+h1.z*h1.z+h1.w*h1.w;
            #pragma unroll
            for (int o = 16; o; o >>= 1){
                s  += __shfl_xor_sync(0xffffffffu, s,  o);
                s2 += __shfl_xor_sync(0xffffffffu, s2, o);
            }
            float mu   = s * (1.f/DD);
            float var  = s2 * (1.f/DD) - mu*mu;
            float rstd = rsqrtf(var + 1e-5f);
            float4 n0, n1;
            n0.x = (h0.x-mu)*rstd*gA.x + bA.x;  n0.y = (h0.y-mu)*rstd*gA.y + bA.y;
            n0.z = (h0.z-mu)*rstd*gA.z + bA.z;  n0.w = (h0.w-mu)*rstd*gA.w + bA.w;
            n1.x = (h1.x-mu)*rstd*gB.x + bB.x;  n1.y = (h1.y-mu)*rstd*gB.y + bB.y;
            n1.z = (h1.z-mu)*rstd*gB.z + bB.z;  n1.w = (h1.w-mu)*rstd*gB.w + bB.w;
            *(float4*)&shn[tok*DD + lane*8]     = n0;
            *(float4*)&shn[tok*DD + lane*8 + 4] = n1;
            *(float4*)&g_hn[(size_t)(tok0+tok)*DD + lane*8]     = n0;
            *(float4*)&g_hn[(size_t)(tok0+tok)*DD + lane*8 + 4] = n1;
        }
    }
    __syncthreads();

    // ---- phase B ----
    {
        int tok = tid >> 4, sub = tid & 15;
        const float* hrow = &shn[tok*DD];
        ull ha[8];
        #pragma unroll
        for (int j = 0; j < 4; j++){
            float4 hv = *(const float4*)&hrow[sub*4 + 64*j];
            asm("mov.b64 %0, {%1, %2};" : "=l"(ha[2*j])   : "f"(hv.x), "f"(hv.y));
            asm("mov.b64 %0, {%1, %2};" : "=l"(ha[2*j+1]) : "f"(hv.z), "f"(hv.w));
        }
        int tg = tok0 + tok;
        float delta = 0.f, myB = 0.f, myC = 0.f;

        #pragma unroll
        for (int c = 0; c <= 16; c++){
            ull a0 = 0ull, a1 = 0ull;
            const float* wr = &sw[c*DD];
            #pragma unroll
            for (int j = 0; j < 4; j++){
                ulonglong2 wv = *(const ulonglong2*)&wr[sub*4 + 64*j];
                FFMA2(a0, ha[2*j],   wv.x);
                FFMA2(a1, ha[2*j+1], wv.y);
            }
            float2 u = unpack2(a0), v = unpack2(a1);
            float ss = (u.x + u.y) + (v.x + v.y);
            ss += __shfl_xor_sync(0xffffffffu, ss, 1);
            ss += __shfl_xor_sync(0xffffffffu, ss, 2);
            ss += __shfl_xor_sync(0xffffffffu, ss, 4);
            ss += __shfl_xor_sync(0xffffffffu, ss, 8);
            if (c == 0)            delta = ss;
            else if (sub == c - 1) myB   = ss;
        }
        delta = softplusf(pd0 + delta);
        g_dB[tg*NXX + sub] = delta * myB;
        if (sub == 0) g_dl2[tg] = delta * 1.44269504088896f;

        #pragma unroll
        for (int c = 17; c < 33; c++){
            ull a0 = 0ull, a1 = 0ull;
            const float* wr = &sw[c*DD];
            #pragma unroll
            for (int j = 0; j < 4; j++){
                ulonglong2 wv = *(const ulonglong2*)&wr[sub*4 + 64*j];
                FFMA2(a0, ha[2*j],   wv.x);
                FFMA2(a1, ha[2*j+1], wv.y);
            }
            float2 u = unpack2(a0), v = unpack2(a1);
            float ss = (u.x + u.y) + (v.x + v.y);
            ss += __shfl_xor_sync(0xffffffffu, ss, 1);
            ss += __shfl_xor_sync(0xffffffffu, ss, 2);
            ss += __shfl_xor_sync(0xffffffffu, ss, 4);
            ss += __shfl_xor_sync(0xffffffffu, ss, 8);
            if (sub == c - 17) myC = ss;
        }
        g_C[tg*NXX + sub] = myC;
    }
}

// =====================================================================
// K2: selective scan — grid (16 d-chunks, 8 batches) x 256 thr (16d x 16n)
// NEW: bank-conflict-free scx layout:
//   float idx = tt*288 + (n>>2)*72 + dl*4 + (n&3)
//   store: 32 distinct banks (1 cyc). tree float4 loads: 4-phase CF (was 16 cyc)
// =====================================================================
__global__ void __launch_bounds__(256) k2(const float* __restrict__ A){
    __shared__ float sdl2[32];
    __shared__ float sdb[32*16];
    __shared__ float sc [32*16];
    __shared__ float su [32*16];
    __shared__ __align__(16) float scx[32*288];
    int tid = threadIdx.x;
    int n = tid & 15, dl = tid >> 4;
    int b = blockIdx.y, d0 = blockIdx.x * 16;
    float a = A[(d0 + dl)*NXX + n];
    float x = 0.f;
    size_t tbase = (size_t)b * LL;
    int soff = (n >> 2)*72 + dl*4 + (n & 3);   // swizzled offset within a tt-row

    // prefetch tile 0 into registers
    float pdb[2], pc[2], pu[2], pdl = 0.f;
    if (tid < 32) pdl = g_dl2[tbase + tid];
    #pragma unroll
    for (int r = 0; r < 2; r++){
        int idx = tid + r*256;
        int tt = idx >> 4, q = idx & 15;
        pdb[r] = g_dB[(tbase + tt)*NXX + q];
        pc [r] = g_C [(tbase + tt)*NXX + q];
        pu [r] = g_hn[(tbase + tt)*DD + d0 + q];
    }

    for (int t0 = 0; t0 < LL; t0 += 32){
        if (tid < 32) sdl2[tid] = pdl;
        #pragma unroll
        for (int r = 0; r < 2; r++){
            int idx = tid + r*256;
            sdb[idx] = pdb[r]; sc[idx] = pc[r]; su[idx] = pu[r];
        }
        __syncthreads();
        if (t0 + 32 < LL){
            int t1 = t0 + 32;
            if (tid < 32) pdl = g_dl2[tbase + t1 + tid];
            #pragma unroll
            for (int r = 0; r < 2; r++){
                int idx = tid + r*256;
                int tt = idx >> 4, q = idx & 15;
                pdb[r] = g_dB[(tbase + t1 + tt)*NXX + q];
                pc [r] = g_C [(tbase + t1 + tt)*NXX + q];
                pu [r] = g_hn[(tbase + t1 + tt)*DD + d0 + q];
            }
        }
        #pragma unroll 4
        for (int tt = 0; tt < 32; tt++){
            float dA  = fexp2(sdl2[tt] * a);
            float dbu = sdb[tt*16 + n] * su[tt*16 + dl];
            x = fmaf(dA, x, dbu);
            scx[tt*288 + soff] = x * sc[tt*16 + n];
        }
        __syncthreads();
        #pragma unroll
        for (int r = 0; r < 2; r++){
            int c = tid + r*256;
            int tt = c >> 4, dd = c & 15;
            const float4* p = (const float4*)&scx[tt*288 + dd*4];
            float4 v0 = p[0], v1 = p[18], v2 = p[36], v3 = p[54];
            float s = ((v0.x+v0.y)+(v0.z+v0.w)) + ((v1.x+v1.y)+(v1.z+v1.w))
                    + ((v2.x+v2.y)+(v2.z+v2.w)) + ((v3.x+v3.y)+(v3.z+v3.w));
            g_upd[(tbase + t0 + tt)*DD + d0 + dd] = s;
        }
        __syncthreads();
    }
}

// =====================================================================
// K34: fused  h2 = LN(h+upd) ;  G = gelu(h2@W1+b1) ;  out = G@W2+b2
// 256 blocks (64 tokens each) x 256 threads
// phase 2 remapped: warp = (token-half wt, col-quarter wc);
//   thread = 4 interleaved tokens (wt*32 + tl + 8i) x 16 cols (wc*64+cl*16..)
//   => A float4 loads conflict-free, B multicast, warps read disjoint cols
// dyn smem: sv[64][260] | Bs[32*256 / W2s 256*32] = 99328 B
// =====================================================================
#define SVS 260
__global__ void __launch_bounds__(256, 2) k34(const float* __restrict__ nfg,
                                              const float* __restrict__ nfb,
                                              const float* __restrict__ W1,
                                              const float* __restrict__ b1,
                                              const float* __restrict__ W2,
                                              const float* __restrict__ b2,
                                              float* __restrict__ out){
    extern __shared__ float sm3[];
    float* sv = sm3;                 // [64][SVS] : LN result, later gelu result
    float* Bs = sm3 + 64*SVS;        // [32][256] W1 chunk, later [256][32] W2

    int tid  = threadIdx.x;
    int tok0 = blockIdx.x * 64;
    int lane = tid & 31, wrp = tid >> 5;

    // ---- phase 1: LN(h + upd) -> sv (unchanged) ----
    {
        float4 gA = *(const float4*)&nfg[lane*8], gB = *(const float4*)&nfg[lane*8+4];
        float4 bA = *(const float4*)&nfb[lane*8], bB = *(const float4*)&nfb[lane*8+4];
        #pragma unroll
        for (int t = 0; t < 8; t++){
            int tok = wrp*8 + t;
            size_t base = (size_t)(tok0 + tok)*DD + lane*8;
            float4 h0 = *(const float4*)&g_h[base];
            float4 h1 = *(const float4*)&g_h[base+4];
            float4 u0 = *(const float4*)&g_upd[base];
            float4 u1 = *(const float4*)&g_upd[base+4];
            float4 v0, v1;
            v0.x=h0.x+u0.x; v0.y=h0.y+u0.y; v0.z=h0.z+u0.z; v0.w=h0.w+u0.w;
            v1.x=h1.x+u1.x; v1.y=h1.y+u1.y; v1.z=h1.z+u1.z; v1.w=h1.w+u1.w;
            float s  = (v0.x+v0.y)+(v0.z+v0.w)+(v1.x+v1.y)+(v1.z+v1.w);
            float s2 = v0.x*v0.x+v0.y*v0.y+v0.z*v0.z+v0.w*v0.w
                     + v1.x*v1.x+v1.y*v1.y+v1.z*v1.z+v1.w*v1.w;
            #pragma unroll
            for (int o = 16; o; o >>= 1){
                s  += __shfl_xor_sync(0xffffffffu, s,  o);
                s2 += __shfl_xor_sync(0xffffffffu, s2, o);
            }
            float mu   = s * (1.f/DD);
            float var  = s2 * (1.f/DD) - mu*mu;
            float rstd = rsqrtf(var + 1e-5f);
            float4 n0, n1;
            n0.x=(v0.x-mu)*rstd*gA.x+bA.x; n0.y=(v0.y-mu)*rstd*gA.y+bA.y;
            n0.z=(v0.z-mu)*rstd*gA.z+bA.z; n0.w=(v0.w-mu)*rstd*gA.w+bA.w;
            n1.x=(v1.x-mu)*rstd*gB.x+bB.x; n1.y=(v1.y-mu)*rstd*gB.y+bB.y;
            n1.z=(v1.z-mu)*rstd*gB.z+bB.z; n1.w=(v1.w-mu)*rstd*gB.w+bB.w;
            *(float4*)&sv[tok*SVS + lane*8]     = n0;
            *(float4*)&sv[tok*SVS + lane*8 + 4] = n1;
        }
    }
    __syncthreads();

    // ---- phase 2: G = gelu(sv @ W1 + b1) — remapped micro-tile ----
    int wc = wrp & 3, wt = wrp >> 2;       // col-quarter, token-half
    int tl = lane >> 2, cl = lane & 3;     // token-lane(8), col-chunk(4)
    int cbase = wc*64 + cl*16;             // this thread's 16 cols
    // tokens: wt*32 + tl + 8*i, i=0..3 (interleaved => conflict-free A loads)
    ull acc[4][8];
    #pragma unroll
    for (int i = 0; i < 4; i++)
        #pragma unroll
        for (int j = 0; j < 8; j++) acc[i][j] = 0ull;

    for (int kk = 0; kk < DD; kk += 32){
        #pragma unroll
        for (int r = 0; r < 8; r++){
            int f4 = tid + r*256;
            int row = f4 >> 6, c4 = (f4 & 63) << 2;
            *(float4*)&Bs[row*256 + c4] =
                *(const float4*)&W1[(size_t)(kk + row)*DD + c4];
        }
        __syncthreads();
        #pragma unroll
        for (int k4 = 0; k4 < 32; k4 += 4){
            float4 av[4];
            #pragma unroll
            for (int i = 0; i < 4; i++)
                av[i] = *(const float4*)&sv[(wt*32 + tl + 8*i)*SVS + kk + k4];
            #pragma unroll
            for (int e = 0; e < 4; e++){
                int k = k4 + e;
                const ulonglong2* br = (const ulonglong2*)&Bs[k*256 + cbase];
                ulonglong2 b0 = br[0], b1v = br[1], b2 = br[2], b3 = br[3];
                #pragma unroll
                for (int i = 0; i < 4; i++){
                    float a = ((const float*)&av[i])[e];
                    ull a2 = packdup(a);
                    FFMA2(acc[i][0], a2, b0.x);  FFMA2(acc[i][1], a2, b0.y);
                    FFMA2(acc[i][2], a2, b1v.x); FFMA2(acc[i][3], a2, b1v.y);
                    FFMA2(acc[i][4], a2, b2.x);  FFMA2(acc[i][5], a2, b2.y);
                    FFMA2(acc[i][6], a2, b3.x);  FFMA2(acc[i][7], a2, b3.y);
                }
            }
        }
        __syncthreads();
    }

    // gelu + bias -> back into sv (row-major, for phase 3)
    {
        float bias[16];
        #pragma unroll
        for (int q = 0; q < 4; q++){
            float4 bb = *(const float4*)&b1[cbase + q*4];
            bias[q*4+0]=bb.x; bias[q*4+1]=bb.y; bias[q*4+2]=bb.z; bias[q*4+3]=bb.w;
        }
        #pragma unroll
        for (int i = 0; i < 4; i++){
            int tok = wt*32 + tl + 8*i;
            float gv[16];
            #pragma unroll
            for (int j = 0; j < 8; j++){
                float2 u = unpack2(acc[i][j]);
                gv[2*j]   = geluf(u.x + bias[2*j]);
                gv[2*j+1] = geluf(u.y + bias[2*j+1]);
            }
            #pragma unroll
            for (int q = 0; q < 4; q++){
                float4 o; o.x=gv[q*4]; o.y=gv[q*4+1]; o.z=gv[q*4+2]; o.w=gv[q*4+3];
                *(float4*)&sv[tok*SVS + cbase + q*4] = o;
            }
        }
    }
    // load W2 into Bs region ([256][32])
    #pragma unroll
    for (int r = 0; r < 8; r++){
        int f4 = (tid + r*256) << 2;
        *(float4*)&Bs[f4] = *(const float4*)&W2[f4];
    }
    __syncthreads();

    // ---- phase 3: out = G @ W2 + b2 (unchanged) ----
    {
        int tok = tid >> 2, og = tid & 3;
        float4 c0 = *(const float4*)&b2[og*8];
        float4 c1 = *(const float4*)&b2[og*8 + 4];
        ull o0, o1, o2, o3;
        asm("mov.b64 %0, {%1, %2};" : "=l"(o0) : "f"(c0.x), "f"(c0.y));
        asm("mov.b64 %0, {%1, %2};" : "=l"(o1) : "f"(c0.z), "f"(c0.w));
        asm("mov.b64 %0, {%1, %2};" : "=l"(o2) : "f"(c1.x), "f"(c1.y));
        asm("mov.b64 %0, {%1, %2};" : "=l"(o3) : "f"(c1.z), "f"(c1.w));
        #pragma unroll 4
        for (int k4 = 0; k4 < DD; k4 += 4){
            float4 g4 = *(const float4*)&sv[tok*SVS + k4];
            float ge[4] = {g4.x, g4.y, g4.z, g4.w};
            #pragma unroll
            for (int e = 0; e < 4; e++){
                ull a2 = packdup(ge[e]);
                const ull* wr = (const ull*)&Bs[(k4 + e)*32 + og*8];
                FFMA2(o0, a2, wr[0]);
                FFMA2(o1, a2, wr[1]);
                FFMA2(o2, a2, wr[2]);
                FFMA2(o3, a2, wr[3]);
            }
        }
        float2 r0 = unpack2(o0), r1 = unpack2(o1), r2 = unpack2(o2), r3 = unpack2(o3);
        float4 w0; w0.x=r0.x; w0.y=r0.y; w0.z=r1.x; w0.w=r1.y;
        float4 w1; w1.x=r2.x; w1.y=r2.y; w1.z=r3.x; w1.w=r3.y;
        size_t ob = (size_t)(tok0 + tok)*32 + og*8;
        *(float4*)&out[ob]     = w0;
        *(float4*)&out[ob + 4] = w1;
    }
}

// ---------------- launcher ----------------
extern "C" void kernel_launch(void* const* d_in, const int* in_sizes, int n_in,
                              void* d_out, int out_size){
    (void)in_sizes; (void)n_in; (void)out_size;
    const float* y    = (const float*)d_in[0];
    const float* Win  = (const float*)d_in[1];
    const float* bin_ = (const float*)d_in[2];
    const float* ng   = (const float*)d_in[3];
    const float* nb   = (const float*)d_in[4];
    const float* A    = (const float*)d_in[5];
    const float* W_B  = (const float*)d_in[6];
    const float* W_C  = (const float*)d_in[7];
    const float* qd   = (const float*)d_in[8];
    const float* pd   = (const float*)d_in[9];
    const float* nfg  = (const float*)d_in[10];
    const float* nfb  = (const float*)d_in[11];
    const float* W1   = (const float*)d_in[12];
    const float* b1   = (const float*)d_in[13];
    const float* W2   = (const float*)d_in[14];
    const float* b2   = (const float*)d_in[15];
    float* out = (float*)d_out;

    cudaFuncSetAttribute(k1ab, cudaFuncAttributeMaxDynamicSharedMemorySize, 68608);
    cudaFuncSetAttribute(k34,  cudaFuncAttributeMaxDynamicSharedMemorySize, 99328);

    k1ab<<<NT/16, 256, 68608>>>(y, Win, bin_, ng, nb, W_B, W_C, qd, pd);
    k2  <<<dim3(DD/16, BB), 256>>>(A);
    k34 <<<NT/64, 256, 99328>>>(nfg, nfb, W1, b1, W2, b2, out);
}